// round 2
// baseline (speedup 1.0000x reference)
#include <cuda_runtime.h>

#define T_SEQ 256
#define NH 8
#define DHD 64
#define DMODEL 512
#define NPROJ 2560   // 5 * 512

// ---------------- scratch (no allocations allowed) ----------------
__device__ float g_proj[T_SEQ * NPROJ];            // [t, 2560]
__device__ float g_M[NH * T_SEQ * DHD * DHD];      // [n, q, k, j]
__device__ float g_G[NH * T_SEQ * DHD * DHD];      // [n, q, a, c]
__device__ float g_l[NH * T_SEQ];                  // softmax denominators
__device__ float g_z[T_SEQ * DMODEL];              // [q, n*64+e] (unnormalized accum)

// ---------------- K0: zero z (atomic accumulation target) ----------------
__global__ __launch_bounds__(256) void zero_z_kernel() {
    g_z[blockIdx.x * 256 + threadIdx.x] = 0.f;
}

// ---------------- K1/generic: C[M,N] = A[M,K] @ B[K,N] + bias[N] ----------------
__global__ __launch_bounds__(256) void gemm_nn_bias_kernel(
    const float* __restrict__ A, const float* __restrict__ B,
    const float* __restrict__ bias, float* __restrict__ C,
    int M, int N, int K) {
    __shared__ float As[64][33];
    __shared__ float Bs[32][65];
    const int tid = threadIdx.x;
    const int bm = blockIdx.y * 64;
    const int bn = blockIdx.x * 64;
    const int r0 = (tid & 15) * 4;
    const int c0 = (tid >> 4) * 4;
    const int arow = tid >> 3;          // 0..31
    const int acol = (tid & 7) * 4;     // 0..28
    const int brow = tid >> 4;          // 0..15
    const int bcol = (tid & 15) * 4;    // 0..60
    float acc[4][4] = {};
    for (int k0 = 0; k0 < K; k0 += 32) {
#pragma unroll
        for (int rr = 0; rr < 2; rr++) {
            float4 v = *reinterpret_cast<const float4*>(&A[(size_t)(bm + arow + rr * 32) * K + k0 + acol]);
            As[arow + rr * 32][acol + 0] = v.x; As[arow + rr * 32][acol + 1] = v.y;
            As[arow + rr * 32][acol + 2] = v.z; As[arow + rr * 32][acol + 3] = v.w;
        }
#pragma unroll
        for (int rr = 0; rr < 2; rr++) {
            float4 v = *reinterpret_cast<const float4*>(&B[(size_t)(k0 + brow + rr * 16) * N + bn + bcol]);
            Bs[brow + rr * 16][bcol + 0] = v.x; Bs[brow + rr * 16][bcol + 1] = v.y;
            Bs[brow + rr * 16][bcol + 2] = v.z; Bs[brow + rr * 16][bcol + 3] = v.w;
        }
        __syncthreads();
#pragma unroll 8
        for (int kk = 0; kk < 32; kk++) {
            float a[4], b[4];
#pragma unroll
            for (int i = 0; i < 4; i++) a[i] = As[r0 + i][kk];
#pragma unroll
            for (int j = 0; j < 4; j++) b[j] = Bs[kk][c0 + j];
#pragma unroll
            for (int i = 0; i < 4; i++)
#pragma unroll
                for (int j = 0; j < 4; j++) acc[i][j] += a[i] * b[j];
        }
        __syncthreads();
    }
#pragma unroll
    for (int i = 0; i < 4; i++)
#pragma unroll
        for (int j = 0; j < 4; j++)
            C[(size_t)(bm + r0 + i) * N + bn + c0 + j] = acc[i][j] + bias[bn + c0 + j];
}

// ---------------- K2: M[n,q,kj] = sum_i qproj[q,i] * Wkq[n,kj,i]  (NT, K=64) ----------------
__global__ __launch_bounds__(256) void compute_M_kernel(const float* __restrict__ Wkq) {
    __shared__ float As[64][65];   // q x i
    __shared__ float Bs[64][65];   // kj x i
    const int n = blockIdx.z;
    const int bq = blockIdx.y * 64;
    const int bkj = blockIdx.x * 64;
    const int tid = threadIdx.x;
    const int row = tid >> 4;          // 0..15
    const int col = (tid & 15) * 4;    // 0..60
#pragma unroll
    for (int rr = 0; rr < 4; rr++) {
        int r = row + rr * 16;
        float4 va = *reinterpret_cast<const float4*>(&g_proj[(size_t)(bq + r) * NPROJ + 1024 + n * 64 + col]);
        As[r][col + 0] = va.x; As[r][col + 1] = va.y; As[r][col + 2] = va.z; As[r][col + 3] = va.w;
        float4 vb = *reinterpret_cast<const float4*>(&Wkq[(size_t)n * 262144 + (size_t)(bkj + r) * 64 + col]);
        Bs[r][col + 0] = vb.x; Bs[r][col + 1] = vb.y; Bs[r][col + 2] = vb.z; Bs[r][col + 3] = vb.w;
    }
    __syncthreads();
    const int q0 = (tid & 15) * 4;
    const int kj0 = (tid >> 4) * 4;
    float acc[4][4] = {};
#pragma unroll 8
    for (int i = 0; i < 64; i++) {
        float a[4], b[4];
#pragma unroll
        for (int ii = 0; ii < 4; ii++) a[ii] = As[q0 + ii][i];
#pragma unroll
        for (int jj = 0; jj < 4; jj++) b[jj] = Bs[kj0 + jj][i];
#pragma unroll
        for (int ii = 0; ii < 4; ii++)
#pragma unroll
            for (int jj = 0; jj < 4; jj++) acc[ii][jj] += a[ii] * b[jj];
    }
#pragma unroll
    for (int ii = 0; ii < 4; ii++)
#pragma unroll
        for (int jj = 0; jj < 4; jj++)
            g_M[(size_t)(n * T_SEQ + bq + q0 + ii) * 4096 + bkj + kj0 + jj] = acc[ii][jj];
}

// ---------------- K3: main attention. One CTA per (head n, query q). ----------------
// smem pool offsets (floats)
#define OFF_K1T 0           // [64][257]  k1 transposed (k, p); later v1s [256][64]
#define OFF_BT  16448       // [64][256]  B transposed (j, p)
#define OFF_ET  32832       // [64][256]  E transposed (t, p); later RT (c, p)
#define OFF_MS  49216       // [64][64]   M (k,j); later k2 tile (t,k)
#define OFF_V2  53312       // [64][64]   v2 tile (t,c)
#define OFF_RED 57408       // [8]
#define ATTN_SMEM_FLOATS 57416
#define ATTN_SMEM_BYTES (ATTN_SMEM_FLOATS * 4)

__global__ __launch_bounds__(256, 1) void attn_kernel() {
    extern __shared__ float sm[];
    float* k1T = sm + OFF_K1T;   // stride 257
    float* BT  = sm + OFF_BT;    // stride 256
    float* ET  = sm + OFF_ET;    // stride 256
    float* Ms  = sm + OFF_MS;    // stride 64
    float* v2s = sm + OFF_V2;    // stride 64
    float* red = sm + OFF_RED;

    const int bid = blockIdx.x;
    const int n = bid & 7;
    const int q = 255 - (bid >> 3);   // big-q CTAs first (most work)
    const int P = q + 1;
    const int tid = threadIdx.x;
    const int pl = tid & 31;          // lane = p-group
    const int tg = tid >> 5;          // warp = t/j/c-group

    // ---- load M (4096 floats) ----
    {
        const float* Mg = g_M + (size_t)(n * T_SEQ + q) * 4096;
        for (int i = tid * 4; i < 4096; i += 1024) {
            float4 v = *reinterpret_cast<const float4*>(&Mg[i]);
            Ms[i + 0] = v.x; Ms[i + 1] = v.y; Ms[i + 2] = v.z; Ms[i + 3] = v.w;
        }
    }
    // ---- load k1 transposed, zero-filled past P ----
    {
        const int rr = tid >> 4;            // 0..15
        const int iv = (tid & 15) * 4;      // 0..60
#pragma unroll
        for (int pass = 0; pass < 16; pass++) {
            int p = pass * 16 + rr;
            float4 v = make_float4(0.f, 0.f, 0.f, 0.f);
            if (p < P) v = *reinterpret_cast<const float4*>(&g_proj[(size_t)p * NPROJ + n * 64 + iv]);
            k1T[(iv + 0) * 257 + p] = v.x;
            k1T[(iv + 1) * 257 + p] = v.y;
            k1T[(iv + 2) * 257 + p] = v.z;
            k1T[(iv + 3) * 257 + p] = v.w;
        }
    }
    __syncthreads();

    // ---- phase 1: B[p,j] = sum_k k1[p,k] * M[k,j] ; store transposed BT[j][p] ----
    {
        float acc[8][8] = {};
#pragma unroll 4
        for (int k = 0; k < 64; k++) {
            float a[8], b[8];
#pragma unroll
            for (int i = 0; i < 8; i++) a[i] = k1T[k * 257 + pl + 32 * i];
#pragma unroll
            for (int j = 0; j < 8; j++) b[j] = Ms[k * 64 + tg + 8 * j];
#pragma unroll
            for (int i = 0; i < 8; i++)
#pragma unroll
                for (int j = 0; j < 8; j++) acc[i][j] += a[i] * b[j];
        }
#pragma unroll
        for (int j = 0; j < 8; j++)
#pragma unroll
            for (int i = 0; i < 8; i++)
                BT[(tg + 8 * j) * 256 + pl + 32 * i] = acc[i][j];
    }
    __syncthreads();

    // ---- phase 2: stream t-tiles; E = exp(S/64) masked; R[p,c] += E @ v2 ----
    float R[8][8] = {};
    float lsum = 0.f;
    const int ntiles = (P + 63) >> 6;
    for (int ti = 0; ti < ntiles; ti++) {
        const int t0 = ti * 64;
        {   // load k2 tile (into Ms region) + v2 tile, zero past P
            const int rr = tid >> 4;
            const int iv = (tid & 15) * 4;
#pragma unroll
            for (int pass = 0; pass < 4; pass++) {
                int t = pass * 16 + rr;
                int gt = t0 + t;
                float4 a = make_float4(0.f, 0.f, 0.f, 0.f);
                float4 b = make_float4(0.f, 0.f, 0.f, 0.f);
                if (gt < P) {
                    a = *reinterpret_cast<const float4*>(&g_proj[(size_t)gt * NPROJ + 512 + n * 64 + iv]);
                    b = *reinterpret_cast<const float4*>(&g_proj[(size_t)gt * NPROJ + 2048 + n * 64 + iv]);
                }
                *reinterpret_cast<float4*>(&Ms[t * 64 + iv]) = a;
                *reinterpret_cast<float4*>(&v2s[t * 64 + iv]) = b;
            }
        }
        __syncthreads();
        // S[p, t_local] = sum_j B[p,j] * k2[t,j]
        float s[8][8] = {};
#pragma unroll 4
        for (int j = 0; j < 64; j++) {
            float a[8], b[8];
#pragma unroll
            for (int i = 0; i < 8; i++) a[i] = BT[j * 256 + pl + 32 * i];
#pragma unroll
            for (int jj = 0; jj < 8; jj++) b[jj] = Ms[(tg + 8 * jj) * 64 + j];
#pragma unroll
            for (int i = 0; i < 8; i++)
#pragma unroll
                for (int jj = 0; jj < 8; jj++) s[i][jj] += a[i] * b[jj];
        }
        // exp + mask + store ET[t][p]; logits ~1e-2 so no max-subtraction needed
#pragma unroll
        for (int i = 0; i < 8; i++) {
            int p = pl + 32 * i;
#pragma unroll
            for (int jj = 0; jj < 8; jj++) {
                int t = t0 + tg + 8 * jj;
                float e = (p < P && t < P) ? __expf(s[i][jj] * 0.015625f) : 0.f;
                lsum += e;
                ET[(tg + 8 * jj) * 256 + p] = e;
            }
        }
        __syncthreads();
        // R[p,c] += sum_t E[p,t] * v2[t,c]
#pragma unroll 4
        for (int t = 0; t < 64; t++) {
            float a[8], b[8];
#pragma unroll
            for (int i = 0; i < 8; i++) a[i] = ET[t * 256 + pl + 32 * i];
#pragma unroll
            for (int j = 0; j < 8; j++) b[j] = v2s[t * 64 + tg + 8 * j];
#pragma unroll
            for (int i = 0; i < 8; i++)
#pragma unroll
                for (int j = 0; j < 8; j++) R[i][j] += a[i] * b[j];
        }
        __syncthreads();
    }

    // ---- stage R transposed RT[c][p] (reuse ET), load v1 (reuse k1T region) ----
#pragma unroll
    for (int j = 0; j < 8; j++)
#pragma unroll
        for (int i = 0; i < 8; i++)
            ET[(tg + 8 * j) * 256 + pl + 32 * i] = R[i][j];
    {
        float* v1s = k1T;   // [256][64], rows >= P never read
        const int rr = tid >> 4;
        const int iv = (tid & 15) * 4;
#pragma unroll
        for (int pass = 0; pass < 16; pass++) {
            int p = pass * 16 + rr;
            if (p < P) {
                float4 v = *reinterpret_cast<const float4*>(&g_proj[(size_t)p * NPROJ + 1536 + n * 64 + iv]);
                *reinterpret_cast<float4*>(&v1s[p * 64 + iv]) = v;
            }
        }
    }
    __syncthreads();

    // ---- phase 3: G[a,c] = sum_{p<P} v1[p,a] * R[p,c] ----
    {
        const float* v1s = k1T;
        const float* RT = ET;
        const int a0 = (tid & 15) * 4;
        const int c0 = (tid >> 4) * 4;
        float acc[4][4] = {};
#pragma unroll 4
        for (int p = 0; p < P; p++) {
            float av[4], rv[4];
#pragma unroll
            for (int k = 0; k < 4; k++) av[k] = v1s[p * 64 + a0 + k];
#pragma unroll
            for (int k = 0; k < 4; k++) rv[k] = RT[(c0 + k) * 256 + p];
#pragma unroll
            for (int ka = 0; ka < 4; ka++)
#pragma unroll
                for (int kc = 0; kc < 4; kc++) acc[ka][kc] += av[ka] * rv[kc];
        }
        float* Gout = g_G + (size_t)(n * T_SEQ + q) * 4096;
#pragma unroll
        for (int ka = 0; ka < 4; ka++)
#pragma unroll
            for (int kc = 0; kc < 4; kc++)
                Gout[(a0 + ka) * 64 + c0 + kc] = acc[ka][kc];
    }

    // ---- softmax denominator reduction ----
#pragma unroll
    for (int off = 16; off > 0; off >>= 1)
        lsum += __shfl_xor_sync(0xffffffffu, lsum, off);
    if (pl == 0) red[tg] = lsum;
    __syncthreads();
    if (tid == 0) {
        float total = 0.f;
#pragma unroll
        for (int w = 0; w < 8; w++) total += red[w];
        g_l[n * T_SEQ + q] = total;
    }
}

// ---------------- K4: z_raw[q, n*64+e] += G[n,q,:] @ W_Vq[n,:,e]  (K-split) ----------------
__global__ __launch_bounds__(256) void out_v_kernel(const float* __restrict__ Wvq) {
    __shared__ float Gs[64][33];
    __shared__ float Ws[32][65];
    const int n = blockIdx.y;
    const int bq = blockIdx.x * 64;
    const int ks = blockIdx.z;          // 4 K-splits of 1024
    const int tid = threadIdx.x;
    const int arow = tid >> 3, acol = (tid & 7) * 4;
    const int brow = tid >> 4, bcol = (tid & 15) * 4;
    float acc[4][4] = {};
    for (int k0 = ks * 1024; k0 < ks * 1024 + 1024; k0 += 32) {
#pragma unroll
        for (int rr = 0; rr < 2; rr++) {
            float4 v = *reinterpret_cast<const float4*>(
                &g_G[(size_t)(n * T_SEQ + bq + arow + rr * 32) * 4096 + k0 + acol]);
            Gs[arow + rr * 32][acol + 0] = v.x; Gs[arow + rr * 32][acol + 1] = v.y;
            Gs[arow + rr * 32][acol + 2] = v.z; Gs[arow + rr * 32][acol + 3] = v.w;
        }
#pragma unroll
        for (int rr = 0; rr < 2; rr++) {
            float4 v = *reinterpret_cast<const float4*>(
                &Wvq[(size_t)n * 262144 + (size_t)(k0 + brow + rr * 16) * 64 + bcol]);
            Ws[brow + rr * 16][bcol + 0] = v.x; Ws[brow + rr * 16][bcol + 1] = v.y;
            Ws[brow + rr * 16][bcol + 2] = v.z; Ws[brow + rr * 16][bcol + 3] = v.w;
        }
        __syncthreads();
#pragma unroll 8
        for (int kk = 0; kk < 32; kk++) {
            float a[4], b[4];
#pragma unroll
            for (int i = 0; i < 4; i++) a[i] = Gs[(tid & 15) * 4 + i][kk];
#pragma unroll
            for (int j = 0; j < 4; j++) b[j] = Ws[kk][(tid >> 4) * 4 + j];
#pragma unroll
            for (int i = 0; i < 4; i++)
#pragma unroll
                for (int j = 0; j < 4; j++) acc[i][j] += a[i] * b[j];
        }
        __syncthreads();
    }
    const int q0 = (tid & 15) * 4, e0 = (tid >> 4) * 4;
#pragma unroll
    for (int i = 0; i < 4; i++)
#pragma unroll
        for (int j = 0; j < 4; j++)
            atomicAdd(&g_z[(size_t)(bq + q0 + i) * DMODEL + n * 64 + e0 + j], acc[i][j]);
}

// ---------------- K5: out = (z_raw * 1/l) @ W_out + b_out ----------------
__global__ __launch_bounds__(256) void gemm_out_kernel(
    const float* __restrict__ Wout, const float* __restrict__ bout, float* __restrict__ C) {
    __shared__ float As[64][33];
    __shared__ float Bs[32][65];
    const int tid = threadIdx.x;
    const int bm = blockIdx.y * 64;
    const int bn = blockIdx.x * 64;
    const int r0 = (tid & 15) * 4;
    const int c0 = (tid >> 4) * 4;
    const int arow = tid >> 3, acol = (tid & 7) * 4;
    const int brow = tid >> 4, bcol = (tid & 15) * 4;
    float acc[4][4] = {};
    for (int k0 = 0; k0 < DMODEL; k0 += 32) {
#pragma unroll
        for (int rr = 0; rr < 2; rr++) {
            int r = bm + arow + rr * 32;          // q
            int gk = k0 + acol;                   // n*64+e (n constant within float4)
            float invl = 1.f / g_l[(gk >> 6) * T_SEQ + r];
            float4 v = *reinterpret_cast<const float4*>(&g_z[(size_t)r * DMODEL + gk]);
            As[arow + rr * 32][acol + 0] = v.x * invl;
            As[arow + rr * 32][acol + 1] = v.y * invl;
            As[arow + rr * 32][acol + 2] = v.z * invl;
            As[arow + rr * 32][acol + 3] = v.w * invl;
        }
#pragma unroll
        for (int rr = 0; rr < 2; rr++) {
            float4 v = *reinterpret_cast<const float4*>(&Wout[(size_t)(k0 + brow + rr * 16) * DMODEL + bn + bcol]);
            Bs[brow + rr * 16][bcol + 0] = v.x; Bs[brow + rr * 16][bcol + 1] = v.y;
            Bs[brow + rr * 16][bcol + 2] = v.z; Bs[brow + rr * 16][bcol + 3] = v.w;
        }
        __syncthreads();
#pragma unroll 8
        for (int kk = 0; kk < 32; kk++) {
            float a[4], b[4];
#pragma unroll
            for (int i = 0; i < 4; i++) a[i] = As[r0 + i][kk];
#pragma unroll
            for (int j = 0; j < 4; j++) b[j] = Bs[kk][c0 + j];
#pragma unroll
            for (int i = 0; i < 4; i++)
#pragma unroll
                for (int j = 0; j < 4; j++) acc[i][j] += a[i] * b[j];
        }
        __syncthreads();
    }
#pragma unroll
    for (int i = 0; i < 4; i++)
#pragma unroll
        for (int j = 0; j < 4; j++)
            C[(size_t)(bm + r0 + i) * DMODEL + bn + c0 + j] = acc[i][j] + bout[bn + c0 + j];
}

// ---------------- launch ----------------
extern "C" void kernel_launch(void* const* d_in, const int* in_sizes, int n_in,
                              void* d_out, int out_size) {
    const float* x       = (const float*)d_in[0];
    const float* Wkkqvv  = (const float*)d_in[1];
    const float* bkkqvv  = (const float*)d_in[2];
    const float* WKq     = (const float*)d_in[3];
    const float* WVq     = (const float*)d_in[4];
    const float* Wout    = (const float*)d_in[5];
    const float* bout    = (const float*)d_in[6];
    float* out = (float*)d_out;

    float* proj_ptr = nullptr;
    cudaGetSymbolAddress((void**)&proj_ptr, g_proj);

    cudaFuncSetAttribute(attn_kernel, cudaFuncAttributeMaxDynamicSharedMemorySize, ATTN_SMEM_BYTES);

    zero_z_kernel<<<T_SEQ * DMODEL / 256, 256>>>();
    gemm_nn_bias_kernel<<<dim3(NPROJ / 64, T_SEQ / 64), 256>>>(x, Wkkqvv, bkkqvv, proj_ptr,
                                                               T_SEQ, NPROJ, DMODEL);
    compute_M_kernel<<<dim3(64, 4, NH), 256>>>(WKq);
    attn_kernel<<<NH * T_SEQ, 256, ATTN_SMEM_BYTES>>>();
    out_v_kernel<<<dim3(4, NH, 4), 256>>>(WVq);
    gemm_out_kernel<<<dim3(DMODEL / 64, T_SEQ / 64), 256>>>(Wout, bout, out);
}

// round 3
// speedup vs baseline: 1.2646x; 1.2646x over previous
#include <cuda_runtime.h>

#define T_SEQ 256
#define NH 8
#define DHD 64
#define DMODEL 512
#define NPROJ 2560   // 5 * 512

// ---------------- scratch (no allocations allowed) ----------------
__device__ float g_proj[T_SEQ * NPROJ];            // [t, 2560]
__device__ float g_M[NH * T_SEQ * DHD * DHD];      // [n, q, k, j]
__device__ float g_G[NH * T_SEQ * DHD * DHD];      // [n, q, a, c]
__device__ float g_l[NH * T_SEQ];                  // softmax denominators
__device__ float g_z[T_SEQ * DMODEL];              // [q, n*64+e] (unnormalized accum)

// ---------------- K0: zero z ----------------
__global__ __launch_bounds__(256) void zero_z_kernel() {
    g_z[blockIdx.x * 256 + threadIdx.x] = 0.f;
}

// ---------------- K1: C[M,N] = A[M,K] @ B[K,N] + bias[N] ----------------
__global__ __launch_bounds__(256) void gemm_nn_bias_kernel(
    const float* __restrict__ A, const float* __restrict__ B,
    const float* __restrict__ bias, float* __restrict__ C,
    int M, int N, int K) {
    __shared__ float As[64][33];
    __shared__ float Bs[32][65];
    const int tid = threadIdx.x;
    const int bm = blockIdx.y * 64;
    const int bn = blockIdx.x * 64;
    const int r0 = (tid & 15) * 4;
    const int c0 = (tid >> 4) * 4;
    const int arow = tid >> 3;
    const int acol = (tid & 7) * 4;
    const int brow = tid >> 4;
    const int bcol = (tid & 15) * 4;
    float acc[4][4] = {};
    for (int k0 = 0; k0 < K; k0 += 32) {
#pragma unroll
        for (int rr = 0; rr < 2; rr++) {
            float4 v = *reinterpret_cast<const float4*>(&A[(size_t)(bm + arow + rr * 32) * K + k0 + acol]);
            As[arow + rr * 32][acol + 0] = v.x; As[arow + rr * 32][acol + 1] = v.y;
            As[arow + rr * 32][acol + 2] = v.z; As[arow + rr * 32][acol + 3] = v.w;
        }
#pragma unroll
        for (int rr = 0; rr < 2; rr++) {
            float4 v = *reinterpret_cast<const float4*>(&B[(size_t)(k0 + brow + rr * 16) * N + bn + bcol]);
            Bs[brow + rr * 16][bcol + 0] = v.x; Bs[brow + rr * 16][bcol + 1] = v.y;
            Bs[brow + rr * 16][bcol + 2] = v.z; Bs[brow + rr * 16][bcol + 3] = v.w;
        }
        __syncthreads();
#pragma unroll 8
        for (int kk = 0; kk < 32; kk++) {
            float a[4], b[4];
#pragma unroll
            for (int i = 0; i < 4; i++) a[i] = As[r0 + i][kk];
#pragma unroll
            for (int j = 0; j < 4; j++) b[j] = Bs[kk][c0 + j];
#pragma unroll
            for (int i = 0; i < 4; i++)
#pragma unroll
                for (int j = 0; j < 4; j++) acc[i][j] += a[i] * b[j];
        }
        __syncthreads();
    }
#pragma unroll
    for (int i = 0; i < 4; i++)
#pragma unroll
        for (int j = 0; j < 4; j++)
            C[(size_t)(bm + r0 + i) * N + bn + c0 + j] = acc[i][j] + bias[bn + c0 + j];
}

// ---------------- K2: M[n,q,kj] = sum_i qproj[q,i] * Wkq[n,kj,i] ----------------
__global__ __launch_bounds__(256) void compute_M_kernel(const float* __restrict__ Wkq) {
    __shared__ float As[64][65];
    __shared__ float Bs[64][65];
    const int n = blockIdx.z;
    const int bq = blockIdx.y * 64;
    const int bkj = blockIdx.x * 64;
    const int tid = threadIdx.x;
    const int row = tid >> 4;
    const int col = (tid & 15) * 4;
#pragma unroll
    for (int rr = 0; rr < 4; rr++) {
        int r = row + rr * 16;
        float4 va = *reinterpret_cast<const float4*>(&g_proj[(size_t)(bq + r) * NPROJ + 1024 + n * 64 + col]);
        As[r][col + 0] = va.x; As[r][col + 1] = va.y; As[r][col + 2] = va.z; As[r][col + 3] = va.w;
        float4 vb = *reinterpret_cast<const float4*>(&Wkq[(size_t)n * 262144 + (size_t)(bkj + r) * 64 + col]);
        Bs[r][col + 0] = vb.x; Bs[r][col + 1] = vb.y; Bs[r][col + 2] = vb.z; Bs[r][col + 3] = vb.w;
    }
    __syncthreads();
    const int q0 = (tid & 15) * 4;
    const int kj0 = (tid >> 4) * 4;
    float acc[4][4] = {};
#pragma unroll 8
    for (int i = 0; i < 64; i++) {
        float a[4], b[4];
#pragma unroll
        for (int ii = 0; ii < 4; ii++) a[ii] = As[q0 + ii][i];
#pragma unroll
        for (int jj = 0; jj < 4; jj++) b[jj] = Bs[kj0 + jj][i];
#pragma unroll
        for (int ii = 0; ii < 4; ii++)
#pragma unroll
            for (int jj = 0; jj < 4; jj++) acc[ii][jj] += a[ii] * b[jj];
    }
#pragma unroll
    for (int ii = 0; ii < 4; ii++)
#pragma unroll
        for (int jj = 0; jj < 4; jj++)
            g_M[(size_t)(n * T_SEQ + bq + q0 + ii) * 4096 + bkj + kj0 + jj] = acc[ii][jj];
}

// ---------------- K3: main attention ----------------
#define OFF_K1T 0           // [64][257]  k1 transposed (k, p); later v1s [256][64]
#define OFF_BT  16448       // [64][256]  B transposed (j, p)
#define OFF_ET  32832       // [64][256]  E transposed (t, p); later RT (c, p)
#define OFF_MS  49216       // [64][64]   M (k,j); later k2 tile (t,j)
#define OFF_V2  53312       // [64][64]   v2 tile (t,c)
#define OFF_RED 57408       // [8]
#define ATTN_SMEM_FLOATS 57416
#define ATTN_SMEM_BYTES (ATTN_SMEM_FLOATS * 4)

// NI = number of 32-wide p register blocks (= 2*ceil(P/64)). p range = NI*32 >= P.
template <int NI>
__device__ __forceinline__ void attn_body(float* sm, int n, int q, int tid) {
    float* k1T = sm + OFF_K1T;   // stride 257
    float* BT  = sm + OFF_BT;    // stride 256
    float* ET  = sm + OFF_ET;    // stride 256
    float* Ms  = sm + OFF_MS;    // stride 64
    float* v2s = sm + OFF_V2;    // stride 64
    float* red = sm + OFF_RED;

    const int P = q + 1;
    const int pl = tid & 31;          // lane -> p
    const int tg = tid >> 5;          // warp
    const int c8 = tg * 8;            // warp's contiguous t/c/j slot

    // ---- load M (4096 floats) ----
    {
        const float* Mg = g_M + (size_t)(n * T_SEQ + q) * 4096;
#pragma unroll
        for (int r = 0; r < 4; r++) {
            int off = (tid + r * 256) * 4;
            *reinterpret_cast<float4*>(&Ms[off]) = *reinterpret_cast<const float4*>(&Mg[off]);
        }
    }
    // ---- load k1 transposed (only p < NI*32), zero-filled past P ----
    {
        const int rr = tid >> 4;
        const int iv = (tid & 15) * 4;
#pragma unroll
        for (int pass = 0; pass < NI * 2; pass++) {
            int p = pass * 16 + rr;
            float4 v = make_float4(0.f, 0.f, 0.f, 0.f);
            if (p < P) v = *reinterpret_cast<const float4*>(&g_proj[(size_t)p * NPROJ + n * 64 + iv]);
            k1T[(iv + 0) * 257 + p] = v.x;
            k1T[(iv + 1) * 257 + p] = v.y;
            k1T[(iv + 2) * 257 + p] = v.z;
            k1T[(iv + 3) * 257 + p] = v.w;
        }
    }
    __syncthreads();

    // ---- phase 1: B[p,j] = sum_k k1[p,k] * M[k,j]; store BT[j][p] ----
    {
        float acc[NI][8];
#pragma unroll
        for (int i = 0; i < NI; i++)
#pragma unroll
            for (int j = 0; j < 8; j++) acc[i][j] = 0.f;
#pragma unroll 4
        for (int k = 0; k < 64; k++) {
            float a[NI];
#pragma unroll
            for (int i = 0; i < NI; i++) a[i] = k1T[k * 257 + pl + 32 * i];
            float4 b0 = *reinterpret_cast<const float4*>(&Ms[k * 64 + c8]);
            float4 b1 = *reinterpret_cast<const float4*>(&Ms[k * 64 + c8 + 4]);
            float b[8] = {b0.x, b0.y, b0.z, b0.w, b1.x, b1.y, b1.z, b1.w};
#pragma unroll
            for (int i = 0; i < NI; i++)
#pragma unroll
                for (int j = 0; j < 8; j++) acc[i][j] += a[i] * b[j];
        }
#pragma unroll
        for (int j = 0; j < 8; j++)
#pragma unroll
            for (int i = 0; i < NI; i++)
                BT[(c8 + j) * 256 + pl + 32 * i] = acc[i][j];
    }
    __syncthreads();

    // ---- phase 2: stream t-tiles; E = exp(S/64) masked; R += E @ v2 ----
    float R[NI][8];
#pragma unroll
    for (int i = 0; i < NI; i++)
#pragma unroll
        for (int j = 0; j < 8; j++) R[i][j] = 0.f;
    float lsum = 0.f;
#pragma unroll 1
    for (int tt = 0; tt < NI / 2; tt++) {
        const int t0 = tt * 64;
        {   // load k2 tile [t][j] into Ms + v2 tile [t][c], zero past P
            const int rr = tid >> 4;
            const int iv = (tid & 15) * 4;
#pragma unroll
            for (int pass = 0; pass < 4; pass++) {
                int t = pass * 16 + rr;
                int gt = t0 + t;
                float4 a = make_float4(0.f, 0.f, 0.f, 0.f);
                float4 b = make_float4(0.f, 0.f, 0.f, 0.f);
                if (gt < P) {
                    a = *reinterpret_cast<const float4*>(&g_proj[(size_t)gt * NPROJ + 512 + n * 64 + iv]);
                    b = *reinterpret_cast<const float4*>(&g_proj[(size_t)gt * NPROJ + 2048 + n * 64 + iv]);
                }
                *reinterpret_cast<float4*>(&Ms[t * 64 + iv]) = a;
                *reinterpret_cast<float4*>(&v2s[t * 64 + iv]) = b;
            }
        }
        __syncthreads();
        // S[p, t=c8+jj] = sum_j B[p,j] * k2[t,j]
        float s[NI][8];
#pragma unroll
        for (int i = 0; i < NI; i++)
#pragma unroll
            for (int j = 0; j < 8; j++) s[i][j] = 0.f;
#pragma unroll 4
        for (int j = 0; j < 64; j++) {
            float a[NI];
#pragma unroll
            for (int i = 0; i < NI; i++) a[i] = BT[j * 256 + pl + 32 * i];
            float b[8];
#pragma unroll
            for (int jj = 0; jj < 8; jj++) b[jj] = Ms[(c8 + jj) * 64 + j];
#pragma unroll
            for (int i = 0; i < NI; i++)
#pragma unroll
                for (int jj = 0; jj < 8; jj++) s[i][jj] += a[i] * b[jj];
        }
        // exp + mask + store ET[t][p]; logits tiny so no max-subtraction needed
#pragma unroll
        for (int i = 0; i < NI; i++) {
            int p = pl + 32 * i;
#pragma unroll
            for (int jj = 0; jj < 8; jj++) {
                int t = t0 + c8 + jj;
                float e = (p < P && t < P) ? __expf(s[i][jj] * 0.015625f) : 0.f;
                lsum += e;
                ET[(c8 + jj) * 256 + p] = e;
            }
        }
        __syncthreads();
        // R[p,c] += sum_t E[p,t] * v2[t,c]
#pragma unroll 4
        for (int t = 0; t < 64; t++) {
            float a[NI];
#pragma unroll
            for (int i = 0; i < NI; i++) a[i] = ET[t * 256 + pl + 32 * i];
            float4 b0 = *reinterpret_cast<const float4*>(&v2s[t * 64 + c8]);
            float4 b1 = *reinterpret_cast<const float4*>(&v2s[t * 64 + c8 + 4]);
            float b[8] = {b0.x, b0.y, b0.z, b0.w, b1.x, b1.y, b1.z, b1.w};
#pragma unroll
            for (int i = 0; i < NI; i++)
#pragma unroll
                for (int j = 0; j < 8; j++) R[i][j] += a[i] * b[j];
        }
        __syncthreads();
    }

    // ---- stage RT[c][p] (reuse ET), load v1 rows (reuse k1T region) ----
#pragma unroll
    for (int j = 0; j < 8; j++)
#pragma unroll
        for (int i = 0; i < NI; i++)
            ET[(c8 + j) * 256 + pl + 32 * i] = R[i][j];
    {
        float* v1s = k1T;   // [256][64], rows >= P never read
        const int rr = tid >> 4;
        const int iv = (tid & 15) * 4;
#pragma unroll
        for (int pass = 0; pass < NI * 2; pass++) {
            int p = pass * 16 + rr;
            if (p < P) {
                float4 v = *reinterpret_cast<const float4*>(&g_proj[(size_t)p * NPROJ + 1536 + n * 64 + iv]);
                *reinterpret_cast<float4*>(&v1s[p * 64 + iv]) = v;
            }
        }
    }
    __syncthreads();

    // ---- phase 3: G[a,c] = sum_{p<P} v1[p,a] * R[p,c] ----
    {
        const float* v1s = k1T;
        const float* RT = ET;
        const int a0 = (tid & 15) * 4;
        const int c0 = (tid >> 4) * 4;
        float acc[4][4] = {};
#pragma unroll 4
        for (int p = 0; p < P; p++) {
            float4 av = *reinterpret_cast<const float4*>(&v1s[p * 64 + a0]);
            float avv[4] = {av.x, av.y, av.z, av.w};
            float rv[4];
#pragma unroll
            for (int k = 0; k < 4; k++) rv[k] = RT[(c0 + k) * 256 + p];
#pragma unroll
            for (int ka = 0; ka < 4; ka++)
#pragma unroll
                for (int kc = 0; kc < 4; kc++) acc[ka][kc] += avv[ka] * rv[kc];
        }
        float* Gout = g_G + (size_t)(n * T_SEQ + q) * 4096;
#pragma unroll
        for (int ka = 0; ka < 4; ka++)
#pragma unroll
            for (int kc = 0; kc < 4; kc++)
                Gout[(a0 + ka) * 64 + c0 + kc] = acc[ka][kc];
    }

    // ---- softmax denominator reduction ----
#pragma unroll
    for (int off = 16; off > 0; off >>= 1)
        lsum += __shfl_xor_sync(0xffffffffu, lsum, off);
    if (pl == 0) red[tg] = lsum;
    __syncthreads();
    if (tid == 0) {
        float total = 0.f;
#pragma unroll
        for (int w = 0; w < 8; w++) total += red[w];
        g_l[n * T_SEQ + q] = total;
    }
}

__global__ __launch_bounds__(256, 1) void attn_kernel() {
    extern __shared__ float sm[];
    const int bid = blockIdx.x;
    const int n = bid & 7;
    const int q = 255 - (bid >> 3);   // big-q CTAs first
    const int ntt = (q >> 6) + 1;     // ceil((q+1)/64)
    switch (ntt) {
        case 1: attn_body<2>(sm, n, q, threadIdx.x); break;
        case 2: attn_body<4>(sm, n, q, threadIdx.x); break;
        case 3: attn_body<6>(sm, n, q, threadIdx.x); break;
        default: attn_body<8>(sm, n, q, threadIdx.x); break;
    }
}

// ---------------- K4: z_raw += G @ W_Vq (K-split) ----------------
__global__ __launch_bounds__(256) void out_v_kernel(const float* __restrict__ Wvq) {
    __shared__ float Gs[64][33];
    __shared__ float Ws[32][65];
    const int n = blockIdx.y;
    const int bq = blockIdx.x * 64;
    const int ks = blockIdx.z;
    const int tid = threadIdx.x;
    const int arow = tid >> 3, acol = (tid & 7) * 4;
    const int brow = tid >> 4, bcol = (tid & 15) * 4;
    float acc[4][4] = {};
    for (int k0 = ks * 1024; k0 < ks * 1024 + 1024; k0 += 32) {
#pragma unroll
        for (int rr = 0; rr < 2; rr++) {
            float4 v = *reinterpret_cast<const float4*>(
                &g_G[(size_t)(n * T_SEQ + bq + arow + rr * 32) * 4096 + k0 + acol]);
            Gs[arow + rr * 32][acol + 0] = v.x; Gs[arow + rr * 32][acol + 1] = v.y;
            Gs[arow + rr * 32][acol + 2] = v.z; Gs[arow + rr * 32][acol + 3] = v.w;
        }
#pragma unroll
        for (int rr = 0; rr < 2; rr++) {
            float4 v = *reinterpret_cast<const float4*>(
                &Wvq[(size_t)n * 262144 + (size_t)(k0 + brow + rr * 16) * 64 + bcol]);
            Ws[brow + rr * 16][bcol + 0] = v.x; Ws[brow + rr * 16][bcol + 1] = v.y;
            Ws[brow + rr * 16][bcol + 2] = v.z; Ws[brow + rr * 16][bcol + 3] = v.w;
        }
        __syncthreads();
#pragma unroll 8
        for (int kk = 0; kk < 32; kk++) {
            float a[4], b[4];
#pragma unroll
            for (int i = 0; i < 4; i++) a[i] = Gs[(tid & 15) * 4 + i][kk];
#pragma unroll
            for (int j = 0; j < 4; j++) b[j] = Ws[kk][(tid >> 4) * 4 + j];
#pragma unroll
            for (int i = 0; i < 4; i++)
#pragma unroll
                for (int j = 0; j < 4; j++) acc[i][j] += a[i] * b[j];
        }
        __syncthreads();
    }
    const int q0 = (tid & 15) * 4, e0 = (tid >> 4) * 4;
#pragma unroll
    for (int i = 0; i < 4; i++)
#pragma unroll
        for (int j = 0; j < 4; j++)
            atomicAdd(&g_z[(size_t)(bq + q0 + i) * DMODEL + n * 64 + e0 + j], acc[i][j]);
}

// ---------------- K5: out = (z_raw * 1/l) @ W_out + b_out ----------------
__global__ __launch_bounds__(256) void gemm_out_kernel(
    const float* __restrict__ Wout, const float* __restrict__ bout, float* __restrict__ C) {
    __shared__ float As[64][33];
    __shared__ float Bs[32][65];
    const int tid = threadIdx.x;
    const int bm = blockIdx.y * 64;
    const int bn = blockIdx.x * 64;
    const int r0 = (tid & 15) * 4;
    const int c0 = (tid >> 4) * 4;
    const int arow = tid >> 3, acol = (tid & 7) * 4;
    const int brow = tid >> 4, bcol = (tid & 15) * 4;
    float acc[4][4] = {};
    for (int k0 = 0; k0 < DMODEL; k0 += 32) {
#pragma unroll
        for (int rr = 0; rr < 2; rr++) {
            int r = bm + arow + rr * 32;
            int gk = k0 + acol;
            float invl = 1.f / g_l[(gk >> 6) * T_SEQ + r];
            float4 v = *reinterpret_cast<const float4*>(&g_z[(size_t)r * DMODEL + gk]);
            As[arow + rr * 32][acol + 0] = v.x * invl;
            As[arow + rr * 32][acol + 1] = v.y * invl;
            As[arow + rr * 32][acol + 2] = v.z * invl;
            As[arow + rr * 32][acol + 3] = v.w * invl;
        }
#pragma unroll
        for (int rr = 0; rr < 2; rr++) {
            float4 v = *reinterpret_cast<const float4*>(&Wout[(size_t)(k0 + brow + rr * 16) * DMODEL + bn + bcol]);
            Bs[brow + rr * 16][bcol + 0] = v.x; Bs[brow + rr * 16][bcol + 1] = v.y;
            Bs[brow + rr * 16][bcol + 2] = v.z; Bs[brow + rr * 16][bcol + 3] = v.w;
        }
        __syncthreads();
#pragma unroll 8
        for (int kk = 0; kk < 32; kk++) {
            float a[4], b[4];
#pragma unroll
            for (int i = 0; i < 4; i++) a[i] = As[r0 + i][kk];
#pragma unroll
            for (int j = 0; j < 4; j++) b[j] = Bs[kk][c0 + j];
#pragma unroll
            for (int i = 0; i < 4; i++)
#pragma unroll
                for (int j = 0; j < 4; j++) acc[i][j] += a[i] * b[j];
        }
        __syncthreads();
    }
#pragma unroll
    for (int i = 0; i < 4; i++)
#pragma unroll
        for (int j = 0; j < 4; j++)
            C[(size_t)(bm + r0 + i) * DMODEL + bn + c0 + j] = acc[i][j] + bout[bn + c0 + j];
}

// ---------------- launch ----------------
extern "C" void kernel_launch(void* const* d_in, const int* in_sizes, int n_in,
                              void* d_out, int out_size) {
    const float* x       = (const float*)d_in[0];
    const float* Wkkqvv  = (const float*)d_in[1];
    const float* bkkqvv  = (const float*)d_in[2];
    const float* WKq     = (const float*)d_in[3];
    const float* WVq     = (const float*)d_in[4];
    const float* Wout    = (const float*)d_in[5];
    const float* bout    = (const float*)d_in[6];
    float* out = (float*)d_out;

    float* proj_ptr = nullptr;
    cudaGetSymbolAddress((void**)&proj_ptr, g_proj);

    cudaFuncSetAttribute(attn_kernel, cudaFuncAttributeMaxDynamicSharedMemorySize, ATTN_SMEM_BYTES);

    zero_z_kernel<<<T_SEQ * DMODEL / 256, 256>>>();
    gemm_nn_bias_kernel<<<dim3(NPROJ / 64, T_SEQ / 64), 256>>>(x, Wkkqvv, bkkqvv, proj_ptr,
                                                               T_SEQ, NPROJ, DMODEL);
    compute_M_kernel<<<dim3(64, 4, NH), 256>>>(WKq);
    attn_kernel<<<NH * T_SEQ, 256, ATTN_SMEM_BYTES>>>();
    out_v_kernel<<<dim3(4, NH, 4), 256>>>(WVq);
    gemm_out_kernel<<<dim3(DMODEL / 64, T_SEQ / 64), 256>>>(Wout, bout, out);
}